// round 6
// baseline (speedup 1.0000x reference)
#include <cuda_runtime.h>

#define T_DIM 1024
#define F_DIM 256
#define F4    (F_DIM / 4)
#define UNITS 32
#define AW    64
#define HALF  32
#define B_DIM 4
#define NROWS (B_DIM * T_DIM)

__device__ float  g_q[NROWS * UNITS];
__device__ float  g_k[NROWS * UNITS];
__device__ float2 g_Wp[2 * (F_DIM / 2) * UNITS];   // packed (W[2fp][u], W[2fp+1][u])

typedef unsigned long long u64;

__device__ __forceinline__ float tanh_approx(float x) {
    float y;
    asm("tanh.approx.f32 %0, %1;" : "=f"(y) : "f"(x));
    return y;
}
__device__ __forceinline__ u64 ffma2(u64 a, u64 b, u64 c) {
    u64 d;
    asm("fma.rn.f32x2 %0, %1, %2, %3;" : "=l"(d) : "l"(a), "l"(b), "l"(c));
    return d;
}
__device__ __forceinline__ float hadd2(u64 v) {
    unsigned lo, hi;
    asm("mov.b64 {%0, %1}, %2;" : "=r"(lo), "=r"(hi) : "l"(v));
    return __uint_as_float(lo) + __uint_as_float(hi);
}
__device__ __forceinline__ void f4_to_u64(float4 v, u64& a, u64& b) {
    asm("mov.b64 %0, {%2, %3};\n\tmov.b64 %1, {%4, %5};"
        : "=l"(a), "=l"(b) : "f"(v.x), "f"(v.y), "f"(v.z), "f"(v.w));
}
__device__ __forceinline__ void u64_to_f4(u64 a, u64 b, float4& v) {
    asm("mov.b64 {%0, %1}, %4;\n\tmov.b64 {%2, %3}, %5;"
        : "=f"(v.x), "=f"(v.y), "=f"(v.z), "=f"(v.w) : "l"(a), "l"(b));
}

// ---------------------------------------------------------------------------
// Kernel 0: pack Wt/Wx into f-pair-interleaved float2 layout.
// ---------------------------------------------------------------------------
__global__ void __launch_bounds__(256) pack_kernel(
    const float* __restrict__ Wt, const float* __restrict__ Wx)
{
    const int idx = blockIdx.x * 256 + threadIdx.x;      // 8192 float2 total
    const int m   = idx >> 12;
    const int r   = idx & 4095;
    const int fp  = r >> 5;
    const int u   = r & 31;
    const float* __restrict__ W = m ? Wx : Wt;
    g_Wp[idx] = make_float2(W[(2 * fp) * UNITS + u], W[(2 * fp + 1) * UNITS + u]);
}

// ---------------------------------------------------------------------------
// Kernel 1: q = x@Wt + bh, k = x@Wx.
// 1024 blocks x 8 warps, 4 rows/block, 1 row per warp (warps 0-3 q, 4-7 k).
// Per f4 iter: 2 LDG.64 + 1 LDS.128 + 2 FFMA2 (two independent acc chains).
// ---------------------------------------------------------------------------
__global__ void __launch_bounds__(256) qk_kernel(
    const float* __restrict__ x, const float* __restrict__ bh)
{
    __shared__ float4 xs4[4 * F4];                       // 4 rows = 4KB

    const int tid = threadIdx.x;
    const int r0  = blockIdx.x * 4;

    const float4* xg = reinterpret_cast<const float4*>(x) + (size_t)r0 * F4;
    xs4[tid] = xg[tid];
    __syncthreads();

    const int  wid  = tid >> 5;
    const int  lane = tid & 31;
    const bool is_q = (wid < 4);
    const int  r    = wid & 3;

    const u64* __restrict__ Wp =
        reinterpret_cast<const u64*>(g_Wp) + (is_q ? 0 : (F_DIM / 2) * UNITS);
    const float4* __restrict__ xr = xs4 + r * F4;

    u64 acc0 = 0ull, acc1 = 0ull;

    #pragma unroll 8
    for (int f4 = 0; f4 < F4; f4++) {
        const u64 w01 = Wp[(2 * f4 + 0) * UNITS + lane]; // LDG.64 coalesced
        const u64 w23 = Wp[(2 * f4 + 1) * UNITS + lane];
        u64 va, vb;
        f4_to_u64(xr[f4], va, vb);                       // LDS.128 broadcast
        acc0 = ffma2(va, w01, acc0);
        acc1 = ffma2(vb, w23, acc1);
    }

    const float bias = is_q ? bh[lane] : 0.f;
    float* __restrict__ G = is_q ? g_q : g_k;
    G[(size_t)(r0 + r) * UNITS + lane] = hadd2(acc0) + hadd2(acc1) + bias;
}

// ---------------------------------------------------------------------------
// Kernel 2 (fused): logits + softmax + v = a @ x for a 4-t tile.
// grid (T/4, B) = 1024 blocks, 256 threads.
// Masked logits get e=-1e30 -> weight exactly 0, so phase D is predicate-free.
// ---------------------------------------------------------------------------
__global__ void __launch_bounds__(256) attn_out_kernel(
    const float* __restrict__ x,
    const float* __restrict__ Wa,
    const float* __restrict__ ba,
    float* __restrict__ out)
{
    const int b  = blockIdx.y;
    const int t0 = blockIdx.x * 4;
    const int sbase = t0 - HALF;
    const int SR = 4 + AW - 1;                   // 67 staged k rows

    __shared__ float  ks[67 * 33];               // padded, conflict-free
    __shared__ float  qs[4 * UNITS];
    __shared__ float  was[UNITS];
    __shared__ float  es[4 * AW];
    __shared__ float2 as2[4 * AW];               // duplicated weight pairs

    const int tid = threadIdx.x;

    for (int idx = tid; idx < SR * UNITS; idx += 256) {
        const int srel = idx >> 5, u = idx & 31;
        int s = sbase + srel;
        s = min(max(s, 0), T_DIM - 1);           // OOB rows masked via es
        ks[srel * 33 + u] = g_k[(size_t)(b * T_DIM + s) * UNITS + u];
    }
    if (tid < 4 * UNITS)
        qs[tid] = g_q[(size_t)(b * T_DIM + t0) * UNITS + tid];
    if (tid < UNITS) was[tid] = Wa[tid];
    __syncthreads();

    // --- logits: one per thread (4 t x 64 j) -------------------------------
    {
        const int tl = tid >> 6;
        const int j  = tid & 63;
        const int s  = t0 + tl - HALF + j;
        float e = -1e30f;
        if (s >= 0 && s < T_DIM) {
            const int srel = tl + j;
            float acc = 0.f;
            #pragma unroll
            for (int u = 0; u < UNITS; u++)
                acc += was[u] * tanh_approx(qs[tl * UNITS + u] + ks[srel * 33 + u]);
            e = acc + ba[0];
        }
        es[tl * AW + j] = e;
    }
    __syncthreads();

    // --- softmax: warps 0-3, one t-row each --------------------------------
    const int wid = tid >> 5, lane = tid & 31;
    if (wid < 4) {
        const float e0 = es[wid * AW + lane];
        const float e1 = es[wid * AW + lane + 32];
        float m = fmaxf(e0, e1);
        #pragma unroll
        for (int o = 16; o; o >>= 1)
            m = fmaxf(m, __shfl_xor_sync(0xffffffffu, m, o));
        const float p0 = __expf(e0 - m);
        const float p1 = __expf(e1 - m);
        float sum = p0 + p1;
        #pragma unroll
        for (int o = 16; o; o >>= 1)
            sum += __shfl_xor_sync(0xffffffffu, sum, o);
        const float inv = 1.f / sum;
        const float a0 = p0 * inv, a1 = p1 * inv;   // 0 for masked entries
        as2[wid * AW + lane]      = make_float2(a0, a0);
        as2[wid * AW + lane + 32] = make_float2(a1, a1);
    }
    __syncthreads();

    // --- phase D: warp = (1 t, 32 of 64 f4 columns) ------------------------
    const int tl    = wid & 3;
    const int f4    = (wid >> 2) * 32 + lane;
    const int tb    = t0 + tl;

    const float4* __restrict__ xg4 =
        reinterpret_cast<const float4*>(x) + (size_t)b * T_DIM * F4;
    const u64* aw = reinterpret_cast<const u64*>(as2 + tl * AW);

    u64 acca = 0ull, accb = 0ull;
    const int sb = tb - HALF;

    #pragma unroll 8
    for (int j = 0; j < AW; j++) {
        int s = sb + j;
        s = min(max(s, 0), T_DIM - 1);           // weight is 0 when OOB
        u64 xa, xb;
        f4_to_u64(__ldg(&xg4[(size_t)s * F4 + f4]), xa, xb);
        const u64 w = aw[j];                     // LDS.64 broadcast, dup pair
        acca = ffma2(xa, w, acca);
        accb = ffma2(xb, w, accb);
    }

    float4 o;
    u64_to_f4(acca, accb, o);
    reinterpret_cast<float4*>(out)[(size_t)(b * T_DIM + tb) * F4 + f4] = o;
}

extern "C" void kernel_launch(void* const* d_in, const int* in_sizes, int n_in,
                              void* d_out, int out_size)
{
    const float* x  = (const float*)d_in[0];
    const float* Wt = (const float*)d_in[1];
    const float* Wx = (const float*)d_in[2];
    const float* bh = (const float*)d_in[3];
    const float* Wa = (const float*)d_in[4];
    const float* ba = (const float*)d_in[5];
    float* out = (float*)d_out;

    pack_kernel<<<32, 256>>>(Wt, Wx);
    qk_kernel<<<NROWS / 4, 256>>>(x, bh);
    attn_out_kernel<<<dim3(T_DIM / 4, B_DIM), 256>>>(x, Wa, ba, out);
}

// round 7
// speedup vs baseline: 1.1404x; 1.1404x over previous
#include <cuda_runtime.h>

#define T_DIM 1024
#define F_DIM 256
#define F4    (F_DIM / 4)
#define UNITS 32
#define AW    64
#define HALF  32
#define B_DIM 4
#define NROWS (B_DIM * T_DIM)

__device__ float g_q[NROWS * UNITS];
__device__ float g_k[NROWS * UNITS];

typedef unsigned long long u64;

__device__ __forceinline__ float tanh_approx(float x) {
    float y;
    asm("tanh.approx.f32 %0, %1;" : "=f"(y) : "f"(x));
    return y;
}
__device__ __forceinline__ u64 ffma2(u64 a, u64 b, u64 c) {
    u64 d;
    asm("fma.rn.f32x2 %0, %1, %2, %3;" : "=l"(d) : "l"(a), "l"(b), "l"(c));
    return d;
}
__device__ __forceinline__ u64 pack2(float a, float b) {
    u64 d;
    asm("mov.b64 %0, {%1, %2};" : "=l"(d) : "f"(a), "f"(b));
    return d;
}
__device__ __forceinline__ float hadd2(u64 v) {
    unsigned lo, hi;
    asm("mov.b64 {%0, %1}, %2;" : "=r"(lo), "=r"(hi) : "l"(v));
    return __uint_as_float(lo) + __uint_as_float(hi);
}
__device__ __forceinline__ void f4_to_u64(float4 v, u64& a, u64& b) {
    asm("mov.b64 %0, {%2, %3};\n\tmov.b64 %1, {%4, %5};"
        : "=l"(a), "=l"(b) : "f"(v.x), "f"(v.y), "f"(v.z), "f"(v.w));
}
__device__ __forceinline__ void u64_to_f4(u64 a, u64 b, float4& v) {
    asm("mov.b64 {%0, %1}, %4;\n\tmov.b64 {%2, %3}, %5;"
        : "=f"(v.x), "=f"(v.y), "=f"(v.z), "=f"(v.w) : "l"(a), "l"(b));
}

// ---------------------------------------------------------------------------
// Kernel 1: q = x@Wt + bh, k = x@Wx. No pre-pack: W packed in registers,
// hoisted over 2 rows per warp. 512 blocks x 8 warps, 8 rows/block.
// Per 16-f chunk: 16 LDG.32 + 8 movs + 2 x (4 LDS.128 + 8 FFMA2).
// ---------------------------------------------------------------------------
__global__ void __launch_bounds__(256) qk_kernel(
    const float* __restrict__ x,
    const float* __restrict__ Wt,
    const float* __restrict__ Wx,
    const float* __restrict__ bh)
{
    __shared__ float4 xs4[8 * F4];                       // 8 rows = 8KB

    const int tid = threadIdx.x;
    const int r0  = blockIdx.x * 8;

    const float4* xg = reinterpret_cast<const float4*>(x) + (size_t)r0 * F4;
    xs4[tid]       = xg[tid];
    xs4[tid + 256] = xg[tid + 256];
    __syncthreads();

    const int  wid  = tid >> 5;
    const int  lane = tid & 31;
    const bool is_q = (wid < 4);
    const int  rp   = wid & 3;                           // row pair 0..3

    const float* __restrict__ W = is_q ? Wt : Wx;        // [F][U]
    const float4* __restrict__ x0 = xs4 + (2 * rp + 0) * F4;
    const float4* __restrict__ x1 = xs4 + (2 * rp + 1) * F4;

    u64 acc0a = 0ull, acc0b = 0ull, acc1a = 0ull, acc1b = 0ull;

    #pragma unroll 2
    for (int c = 0; c < 16; c++) {                       // 16 f per chunk
        u64 w[8];
        #pragma unroll
        for (int ff = 0; ff < 8; ff++) {
            const float wa = W[(c * 16 + 2 * ff + 0) * UNITS + lane];
            const float wb = W[(c * 16 + 2 * ff + 1) * UNITS + lane];
            w[ff] = pack2(wa, wb);
        }
        #pragma unroll
        for (int k = 0; k < 4; k++) {
            u64 va, vb;
            f4_to_u64(x0[c * 4 + k], va, vb);            // LDS.128 broadcast
            acc0a = ffma2(va, w[2 * k + 0], acc0a);
            acc0b = ffma2(vb, w[2 * k + 1], acc0b);
            f4_to_u64(x1[c * 4 + k], va, vb);
            acc1a = ffma2(va, w[2 * k + 0], acc1a);
            acc1b = ffma2(vb, w[2 * k + 1], acc1b);
        }
    }

    const float bias = is_q ? bh[lane] : 0.f;
    float* __restrict__ G = is_q ? g_q : g_k;
    G[(size_t)(r0 + 2 * rp + 0) * UNITS + lane] = hadd2(acc0a) + hadd2(acc0b) + bias;
    G[(size_t)(r0 + 2 * rp + 1) * UNITS + lane] = hadd2(acc1a) + hadd2(acc1b) + bias;
}

// ---------------------------------------------------------------------------
// Kernel 2 (fused): logits + softmax + v = a @ x for an 8-t tile.
// grid (T/8, B) = 512 blocks, 256 threads.
// Weights stored as zero-padded dup-pairs -> predicate-free phase D.
// ---------------------------------------------------------------------------
__global__ void __launch_bounds__(256) attn_out_kernel(
    const float* __restrict__ x,
    const float* __restrict__ Wa,
    const float* __restrict__ ba,
    float* __restrict__ out)
{
    const int b  = blockIdx.y;
    const int t0 = blockIdx.x * 8;
    const int sbase = t0 - HALF;
    const int SR = 8 + AW - 1;                   // 71 staged k rows
    const int AP = AW + 2;                       // padded weight stride

    __shared__ float ks[71 * 33];                // padded, conflict-free
    __shared__ float qs[8 * UNITS];
    __shared__ float was[UNITS];
    __shared__ float es[8 * AW];
    __shared__ u64   as2[8 * AP];                // dup pairs, zeros at [0],[65]

    const int tid = threadIdx.x;

    for (int idx = tid; idx < SR * UNITS; idx += 256) {
        const int srel = idx >> 5, u = idx & 31;
        int s = sbase + srel;
        s = min(max(s, 0), T_DIM - 1);           // OOB rows masked via es
        ks[srel * 33 + u] = g_k[(size_t)(b * T_DIM + s) * UNITS + u];
    }
    if (tid < 8 * UNITS)
        qs[tid] = g_q[(size_t)(b * T_DIM + t0) * UNITS + tid];
    if (tid < UNITS) was[tid] = Wa[tid];
    __syncthreads();

    // --- logits: 2 per thread (8 t x 64 j = 512) ---------------------------
    #pragma unroll
    for (int l = 0; l < 2; l++) {
        const int idx = tid + l * 256;
        const int tl  = idx >> 6;
        const int j   = idx & 63;
        const int s   = t0 + tl - HALF + j;
        float e = -1e30f;
        if (s >= 0 && s < T_DIM) {
            const int srel = tl + j;
            float acc = 0.f;
            #pragma unroll
            for (int u = 0; u < UNITS; u++)
                acc += was[u] * tanh_approx(qs[tl * UNITS + u] + ks[srel * 33 + u]);
            e = acc + ba[0];
        }
        es[tl * AW + j] = e;
    }
    __syncthreads();

    // --- softmax: 8 warps, one t each; write zero-padded dup pairs ---------
    const int wid = tid >> 5, lane = tid & 31;
    {
        const float e0 = es[wid * AW + lane];
        const float e1 = es[wid * AW + lane + 32];
        float m = fmaxf(e0, e1);
        #pragma unroll
        for (int o = 16; o; o >>= 1)
            m = fmaxf(m, __shfl_xor_sync(0xffffffffu, m, o));
        const float p0 = __expf(e0 - m);
        const float p1 = __expf(e1 - m);
        float sum = p0 + p1;
        #pragma unroll
        for (int o = 16; o; o >>= 1)
            sum += __shfl_xor_sync(0xffffffffu, sum, o);
        const float inv = 1.f / sum;
        const float a0 = p0 * inv, a1 = p1 * inv;   // exactly 0 when masked
        as2[wid * AP + 1 + lane]      = pack2(a0, a0);
        as2[wid * AP + 33 + lane]     = pack2(a1, a1);
        if (lane == 0) {
            as2[wid * AP + 0]      = 0ull;          // pad left
            as2[wid * AP + AW + 1] = 0ull;          // pad right
        }
    }
    __syncthreads();

    // --- phase D: warp = (2 t, f-half). Union window 65 rows. --------------
    const int p  = wid & 3;                      // t pair: 2p, 2p+1
    const int h  = wid >> 2;
    const int f4 = h * 32 + lane;
    const int ta = t0 + 2 * p;

    const float4* __restrict__ xg4 =
        reinterpret_cast<const float4*>(x) + (size_t)b * T_DIM * F4;
    const u64* awa = as2 + (2 * p + 0) * AP;     // index [1+i]
    const u64* awb = as2 + (2 * p + 1) * AP;     // index [i]

    u64 acc0a = 0ull, acc0b = 0ull, acc1a = 0ull, acc1b = 0ull;

    if (t0 >= HALF && t0 + 7 + HALF < T_DIM) {
        // ---- interior fast path: no clamps, pointer walk ----
        const float4* xp = xg4 + (size_t)(ta - HALF) * F4 + f4;
        #pragma unroll 5
        for (int i = 0; i < AW + 1; i++) {
            u64 xa, xb;
            f4_to_u64(*xp, xa, xb);              // LDG.128
            xp += F4;
            const u64 w0 = awa[i + 1];           // LDS.64 dup pair
            const u64 w1 = awb[i];
            acc0a = ffma2(xa, w0, acc0a);
            acc0b = ffma2(xb, w0, acc0b);
            acc1a = ffma2(xa, w1, acc1a);
            acc1b = ffma2(xb, w1, acc1b);
        }
    } else {
        // ---- boundary path: clamp s; OOB weights are exactly 0 ----
        #pragma unroll 5
        for (int i = 0; i < AW + 1; i++) {
            int s = ta - HALF + i;
            s = min(max(s, 0), T_DIM - 1);
            u64 xa, xb;
            f4_to_u64(xg4[(size_t)s * F4 + f4], xa, xb);
            const u64 w0 = awa[i + 1];
            const u64 w1 = awb[i];
            acc0a = ffma2(xa, w0, acc0a);
            acc0b = ffma2(xb, w0, acc0b);
            acc1a = ffma2(xa, w1, acc1a);
            acc1b = ffma2(xb, w1, acc1b);
        }
    }

    float4 o0, o1;
    u64_to_f4(acc0a, acc0b, o0);
    u64_to_f4(acc1a, acc1b, o1);
    float4* __restrict__ og =
        reinterpret_cast<float4*>(out) + (size_t)b * T_DIM * F4;
    og[(size_t)(ta + 0) * F4 + f4] = o0;
    og[(size_t)(ta + 1) * F4 + f4] = o1;
}

extern "C" void kernel_launch(void* const* d_in, const int* in_sizes, int n_in,
                              void* d_out, int out_size)
{
    const float* x  = (const float*)d_in[0];
    const float* Wt = (const float*)d_in[1];
    const float* Wx = (const float*)d_in[2];
    const float* bh = (const float*)d_in[3];
    const float* Wa = (const float*)d_in[4];
    const float* ba = (const float*)d_in[5];
    float* out = (float*)d_out;

    qk_kernel<<<NROWS / 8, 256>>>(x, Wt, Wx, bh);
    attn_out_kernel<<<dim3(T_DIM / 8, B_DIM), 256>>>(x, Wa, ba, out);
}